// round 1
// baseline (speedup 1.0000x reference)
#include <cuda_runtime.h>
#include <math.h>

#define NS 2048
#define VDIM 8192

// ---- scratch (device globals; no allocation allowed) ----
__device__ float g_S[NS * 9];       // R^T Lq R per site
__device__ float g_R[NS * 9];       // rotation per site
__device__ float g_Lq[NS * 9];      // Lambda_q per site
__device__ float g_Abase[NS * 9];   // Lambda_p + Lambda_o per site
__device__ float g_C[NS * 9];       // beta @ S per row
__device__ float g_colpart[16 * NS];// partial column sums of beta

// ---- 3x3 helpers ----
__device__ __forceinline__ void inv3(const float* a, float* o) {
    float c00 = a[4] * a[8] - a[5] * a[7];
    float c01 = a[5] * a[6] - a[3] * a[8];
    float c02 = a[3] * a[7] - a[4] * a[6];
    float det = a[0] * c00 + a[1] * c01 + a[2] * c02;
    float id = 1.0f / det;
    o[0] = c00 * id;
    o[1] = (a[2] * a[7] - a[1] * a[8]) * id;
    o[2] = (a[1] * a[5] - a[2] * a[4]) * id;
    o[3] = c01 * id;
    o[4] = (a[0] * a[8] - a[2] * a[6]) * id;
    o[5] = (a[2] * a[3] - a[0] * a[5]) * id;
    o[6] = c02 * id;
    o[7] = (a[1] * a[6] - a[0] * a[7]) * id;
    o[8] = (a[0] * a[4] - a[1] * a[3]) * id;
}

__device__ __forceinline__ void mm3(const float* A, const float* B, float* O) {
#pragma unroll
    for (int r = 0; r < 3; r++)
#pragma unroll
        for (int c = 0; c < 3; c++)
            O[r * 3 + c] = A[r * 3 + 0] * B[0 + c] + A[r * 3 + 1] * B[3 + c] + A[r * 3 + 2] * B[6 + c];
}

// O = A^T * B
__device__ __forceinline__ void mTm3(const float* A, const float* B, float* O) {
#pragma unroll
    for (int r = 0; r < 3; r++)
#pragma unroll
        for (int c = 0; c < 3; c++)
            O[r * 3 + c] = A[0 + r] * B[0 + c] + A[3 + r] * B[3 + c] + A[6 + r] * B[6 + c];
}

// O = A * B^T
__device__ __forceinline__ void mmT3(const float* A, const float* B, float* O) {
#pragma unroll
    for (int r = 0; r < 3; r++)
#pragma unroll
        for (int c = 0; c < 3; c++)
            O[r * 3 + c] = A[r * 3 + 0] * B[c * 3 + 0] + A[r * 3 + 1] * B[c * 3 + 1] + A[r * 3 + 2] * B[c * 3 + 2];
}

// Rodrigues: R = exp([phi]x)
__device__ __forceinline__ void rodrigues(float x, float y, float z, float* R) {
    float t2 = x * x + y * y + z * z;
    float A, B;
    if (t2 < 1e-12f) {
        A = 1.0f - t2 * (1.0f / 6.0f);
        B = 0.5f - t2 * (1.0f / 24.0f);
    } else {
        float t = sqrtf(t2);
        A = sinf(t) / t;
        B = (1.0f - cosf(t)) / t2;
    }
    R[0] = 1.0f - B * (y * y + z * z);
    R[1] = -A * z + B * x * y;
    R[2] = A * y + B * x * z;
    R[3] = A * z + B * x * y;
    R[4] = 1.0f - B * (x * x + z * z);
    R[5] = -A * x + B * y * z;
    R[6] = -A * y + B * x * z;
    R[7] = A * x + B * y * z;
    R[8] = 1.0f - B * (x * x + y * y);
}

// ---- K1: per-site Lambda_p, Lambda_q, R, S, Lambda_o ----
// 256 blocks x 256 threads; warp-per-site (8 sites/block); W_out chunked in smem.
__global__ void __launch_bounds__(256) site_kernel(
    const float* __restrict__ Sp, const float* __restrict__ Sq,
    const float* __restrict__ phi, const float* __restrict__ mu,
    const float* __restrict__ W) {
    __shared__ float sW[2048 * 3];
    const int warp = threadIdx.x >> 5;
    const int lane = threadIdx.x & 31;
    const int site = blockIdx.x * 8 + warp;

    const float mu0 = mu[site * 3 + 0];
    const float mu1 = mu[site * 3 + 1];
    const float mu2 = mu[site * 3 + 2];

    float Z = 0.f, sw0 = 0.f, sw1 = 0.f, sw2 = 0.f;
    float s00 = 0.f, s01 = 0.f, s02 = 0.f, s11 = 0.f, s12 = 0.f, s22 = 0.f;

    for (int ch = 0; ch < 4; ch++) {
        __syncthreads();
        for (int idx = threadIdx.x; idx < 6144; idx += 256)
            sW[idx] = W[ch * 6144 + idx];
        __syncthreads();
#pragma unroll 4
        for (int v = lane; v < 2048; v += 32) {
            float w0 = sW[v * 3 + 0];
            float w1 = sW[v * 3 + 1];
            float w2 = sW[v * 3 + 2];
            float l = mu0 * w0 + mu1 * w1 + mu2 * w2;
            float e = __expf(l);
            Z += e;
            float t0 = e * w0, t1 = e * w1, t2 = e * w2;
            sw0 += t0; sw1 += t1; sw2 += t2;
            s00 += t0 * w0; s01 += t0 * w1; s02 += t0 * w2;
            s11 += t1 * w1; s12 += t1 * w2; s22 += t2 * w2;
        }
    }
#pragma unroll
    for (int off = 16; off; off >>= 1) {
        Z += __shfl_xor_sync(~0u, Z, off);
        sw0 += __shfl_xor_sync(~0u, sw0, off);
        sw1 += __shfl_xor_sync(~0u, sw1, off);
        sw2 += __shfl_xor_sync(~0u, sw2, off);
        s00 += __shfl_xor_sync(~0u, s00, off);
        s01 += __shfl_xor_sync(~0u, s01, off);
        s02 += __shfl_xor_sync(~0u, s02, off);
        s11 += __shfl_xor_sync(~0u, s11, off);
        s12 += __shfl_xor_sync(~0u, s12, off);
        s22 += __shfl_xor_sync(~0u, s22, off);
    }

    if (lane == 0) {
        float Zi = 1.0f / Z;
        float m0 = sw0 * Zi, m1 = sw1 * Zi, m2 = sw2 * Zi;
        float Lo[9];
        Lo[0] = s00 * Zi - m0 * m0 + 1e-6f;
        Lo[1] = s01 * Zi - m0 * m1;
        Lo[2] = s02 * Zi - m0 * m2;
        Lo[3] = Lo[1];
        Lo[4] = s11 * Zi - m1 * m1 + 1e-6f;
        Lo[5] = s12 * Zi - m1 * m2;
        Lo[6] = Lo[2];
        Lo[7] = Lo[5];
        Lo[8] = s22 * Zi - m2 * m2 + 1e-6f;

        // Lambda_p = inv(Sigma_p + eps I)
        float a[9], Lp[9];
#pragma unroll
        for (int k = 0; k < 9; k++) a[k] = Sp[site * 9 + k];
        a[0] += 1e-6f; a[4] += 1e-6f; a[8] += 1e-6f;
        inv3(a, Lp);

        // Lambda_q = inv(Sigma_q + eps I)
        float Lq[9];
#pragma unroll
        for (int k = 0; k < 9; k++) a[k] = Sq[site * 9 + k];
        a[0] += 1e-6f; a[4] += 1e-6f; a[8] += 1e-6f;
        inv3(a, Lq);

        // R = exp([phi]x)
        float R[9];
        rodrigues(phi[site * 3 + 0], phi[site * 3 + 1], phi[site * 3 + 2], R);

        // S = R^T Lq R
        float T[9], Smat[9];
        mm3(Lq, R, T);
        mTm3(R, T, Smat);

#pragma unroll
        for (int k = 0; k < 9; k++) {
            g_Abase[site * 9 + k] = Lp[k] + Lo[k];
            g_Lq[site * 9 + k] = Lq[k];
            g_R[site * 9 + k] = R[k];
            g_S[site * 9 + k] = Smat[k];
        }
    }
}

// ---- K2: column-sum partials of beta ----
// grid (8, 16): x = j-tile of 256, y = i-chunk of 128
__global__ void __launch_bounds__(256) colsum_kernel(const float* __restrict__ beta) {
    int j = blockIdx.x * 256 + threadIdx.x;
    int i0 = blockIdx.y * 128;
    float s = 0.f;
#pragma unroll 8
    for (int i = 0; i < 128; i++)
        s += beta[(size_t)(i0 + i) * NS + j];
    g_colpart[blockIdx.y * NS + j] = s;
}

// ---- K3: C = beta @ S  (2048x2048 @ 2048x9) ----
// 128 blocks x 512 threads; warp-per-row (16 rows/block); S chunked in smem.
__global__ void __launch_bounds__(512) betaS_kernel(const float* __restrict__ beta) {
    __shared__ float sS[1024 * 9];
    const int warp = threadIdx.x >> 5;
    const int lane = threadIdx.x & 31;
    const int row = blockIdx.x * 16 + warp;

    float c[9];
#pragma unroll
    for (int k = 0; k < 9; k++) c[k] = 0.f;

    for (int ch = 0; ch < 2; ch++) {
        __syncthreads();
        for (int idx = threadIdx.x; idx < 9216; idx += 512)
            sS[idx] = g_S[ch * 9216 + idx];
        __syncthreads();
        const float* brow = beta + (size_t)row * NS + ch * 1024;
#pragma unroll 2
        for (int jj = lane; jj < 1024; jj += 32) {
            float b = brow[jj];
            const float* s = &sS[jj * 9];
#pragma unroll
            for (int k = 0; k < 9; k++) c[k] += b * s[k];
        }
    }
#pragma unroll
    for (int k = 0; k < 9; k++)
#pragma unroll
        for (int off = 16; off; off >>= 1)
            c[k] += __shfl_xor_sync(~0u, c[k], off);

    if (lane == 0) {
#pragma unroll
        for (int k = 0; k < 9; k++) g_C[row * 9 + k] = c[k];
    }
}

// ---- K4: assemble M, M_pd = M (clip provably inactive), M_inv = inv3(M) ----
__global__ void __launch_bounds__(256) final_kernel(float* __restrict__ out) {
    int i = blockIdx.x * 256 + threadIdx.x;
    if (i >= NS) return;

    float cs = 0.f;
#pragma unroll
    for (int p = 0; p < 16; p++) cs += g_colpart[p * NS + i];

    float R[9], C[9], Lq[9], Ab[9];
#pragma unroll
    for (int k = 0; k < 9; k++) {
        R[k] = g_R[i * 9 + k];
        C[k] = g_C[i * 9 + k];
        Lq[k] = g_Lq[i * 9 + k];
        Ab[k] = g_Abase[i * 9 + k];
    }

    // M_in = R C R^T
    float T[9], Min[9];
    mm3(R, C, T);
    mmT3(T, R, Min);

    float M[9];
#pragma unroll
    for (int k = 0; k < 9; k++) M[k] = Ab[k] + Min[k] + cs * Lq[k];

    // symmetrize
    float Ms[9];
#pragma unroll
    for (int r = 0; r < 3; r++)
#pragma unroll
        for (int c = 0; c < 3; c++)
            Ms[r * 3 + c] = 0.5f * (M[r * 3 + c] + M[c * 3 + r]);

    // finite guard (elementwise replace with I), then + 1e-4 I
#pragma unroll
    for (int k = 0; k < 9; k++)
        if (!isfinite(Ms[k])) Ms[k] = (k == 0 || k == 4 || k == 8) ? 1.0f : 0.0f;
    Ms[0] += 1e-4f; Ms[4] += 1e-4f; Ms[8] += 1e-4f;

    float Mi[9];
    inv3(Ms, Mi);

#pragma unroll
    for (int k = 0; k < 9; k++) {
        out[i * 9 + k] = Ms[k];
        out[NS * 9 + i * 9 + k] = Mi[k];
    }
}

extern "C" void kernel_launch(void* const* d_in, const int* in_sizes, int n_in,
                              void* d_out, int out_size) {
    const float* Sp = (const float*)d_in[0];
    const float* Sq = (const float*)d_in[1];
    const float* phi = (const float*)d_in[2];
    const float* beta = (const float*)d_in[3];
    const float* mu = (const float*)d_in[4];
    const float* W = (const float*)d_in[5];
    float* out = (float*)d_out;

    site_kernel<<<256, 256>>>(Sp, Sq, phi, mu, W);
    colsum_kernel<<<dim3(8, 16), 256>>>(beta);
    betaS_kernel<<<128, 512>>>(beta);
    final_kernel<<<8, 256>>>(out);
}

// round 2
// speedup vs baseline: 1.3409x; 1.3409x over previous
#include <cuda_runtime.h>
#include <math.h>

#define NS 2048

// ---- scratch (device globals; no allocation allowed) ----
__device__ float g_S[NS * 9];        // R^T Lq R per site
__device__ float g_R[NS * 9];        // rotation per site
__device__ float g_Lq[NS * 9];       // Lambda_q per site
__device__ float g_Abase[NS * 9];    // Lambda_p + Lambda_o per site
__device__ float g_colpart[32 * NS]; // partial column sums of beta

// ---- packed f32x2 helpers (sm_103a) ----
typedef unsigned long long ull;
__device__ __forceinline__ ull pk2(float a, float b) {
    ull r; asm("mov.b64 %0, {%1,%2};" : "=l"(r) : "f"(a), "f"(b)); return r;
}
__device__ __forceinline__ void upk2(ull p, float& a, float& b) {
    asm("mov.b64 {%0,%1}, %2;" : "=f"(a), "=f"(b) : "l"(p));
}
__device__ __forceinline__ ull fma2(ull a, ull b, ull c) {
    ull r; asm("fma.rn.f32x2 %0, %1, %2, %3;" : "=l"(r) : "l"(a), "l"(b), "l"(c)); return r;
}
__device__ __forceinline__ ull mul2(ull a, ull b) {
    ull r; asm("mul.rn.f32x2 %0, %1, %2;" : "=l"(r) : "l"(a), "l"(b)); return r;
}
__device__ __forceinline__ ull add2(ull a, ull b) {
    ull r; asm("add.rn.f32x2 %0, %1, %2;" : "=l"(r) : "l"(a), "l"(b)); return r;
}

// ---- 3x3 helpers ----
__device__ __forceinline__ void inv3(const float* a, float* o) {
    float c00 = a[4] * a[8] - a[5] * a[7];
    float c01 = a[5] * a[6] - a[3] * a[8];
    float c02 = a[3] * a[7] - a[4] * a[6];
    float det = a[0] * c00 + a[1] * c01 + a[2] * c02;
    float id = 1.0f / det;
    o[0] = c00 * id;
    o[1] = (a[2] * a[7] - a[1] * a[8]) * id;
    o[2] = (a[1] * a[5] - a[2] * a[4]) * id;
    o[3] = c01 * id;
    o[4] = (a[0] * a[8] - a[2] * a[6]) * id;
    o[5] = (a[2] * a[3] - a[0] * a[5]) * id;
    o[6] = c02 * id;
    o[7] = (a[1] * a[6] - a[0] * a[7]) * id;
    o[8] = (a[0] * a[4] - a[1] * a[3]) * id;
}

__device__ __forceinline__ void mm3(const float* A, const float* B, float* O) {
#pragma unroll
    for (int r = 0; r < 3; r++)
#pragma unroll
        for (int c = 0; c < 3; c++)
            O[r * 3 + c] = A[r * 3 + 0] * B[0 + c] + A[r * 3 + 1] * B[3 + c] + A[r * 3 + 2] * B[6 + c];
}
__device__ __forceinline__ void mTm3(const float* A, const float* B, float* O) {
#pragma unroll
    for (int r = 0; r < 3; r++)
#pragma unroll
        for (int c = 0; c < 3; c++)
            O[r * 3 + c] = A[0 + r] * B[0 + c] + A[3 + r] * B[3 + c] + A[6 + r] * B[6 + c];
}
__device__ __forceinline__ void mmT3(const float* A, const float* B, float* O) {
#pragma unroll
    for (int r = 0; r < 3; r++)
#pragma unroll
        for (int c = 0; c < 3; c++)
            O[r * 3 + c] = A[r * 3 + 0] * B[c * 3 + 0] + A[r * 3 + 1] * B[c * 3 + 1] + A[r * 3 + 2] * B[c * 3 + 2];
}

__device__ __forceinline__ void rodrigues(float x, float y, float z, float* R) {
    float t2 = x * x + y * y + z * z;
    float A, B;
    if (t2 < 1e-12f) {
        A = 1.0f - t2 * (1.0f / 6.0f);
        B = 0.5f - t2 * (1.0f / 24.0f);
    } else {
        float t = sqrtf(t2);
        A = sinf(t) / t;
        B = (1.0f - cosf(t)) / t2;
    }
    R[0] = 1.0f - B * (y * y + z * z);
    R[1] = -A * z + B * x * y;
    R[2] = A * y + B * x * z;
    R[3] = A * z + B * x * y;
    R[4] = 1.0f - B * (x * x + z * z);
    R[5] = -A * x + B * y * z;
    R[6] = -A * y + B * x * z;
    R[7] = A * x + B * y * z;
    R[8] = 1.0f - B * (x * x + y * y);
}

// ==== K1: blocks 0..255 = per-site stats (warp/site); blocks 256..287 = beta colsum ====
__global__ void __launch_bounds__(256) k1_kernel(
    const float* __restrict__ Sp, const float* __restrict__ Sq,
    const float* __restrict__ phi, const float* __restrict__ mu,
    const float* __restrict__ W, const float* __restrict__ beta) {
    __shared__ float sW0[2048];
    __shared__ float sW1[2048];
    __shared__ float sW2[2048];

    if (blockIdx.x >= 256) {
        // ---- colsum part: 32 blocks, 64 rows each ----
        const int b = blockIdx.x - 256;
        const int i0 = b * 64;
        const int t = threadIdx.x;
        float4 a0 = make_float4(0.f, 0.f, 0.f, 0.f);
        float4 a1 = make_float4(0.f, 0.f, 0.f, 0.f);
#pragma unroll 4
        for (int i = 0; i < 64; i++) {
            const float4* row = (const float4*)(beta + (size_t)(i0 + i) * NS);
            float4 v0 = row[t];
            float4 v1 = row[t + 256];
            a0.x += v0.x; a0.y += v0.y; a0.z += v0.z; a0.w += v0.w;
            a1.x += v1.x; a1.y += v1.y; a1.z += v1.z; a1.w += v1.w;
        }
        ((float4*)(g_colpart + b * NS))[t] = a0;
        ((float4*)(g_colpart + b * NS))[t + 256] = a1;
        return;
    }

    const int warp = threadIdx.x >> 5;
    const int lane = threadIdx.x & 31;
    const int site = blockIdx.x * 8 + warp;

    const float mu0 = mu[site * 3 + 0];
    const float mu1 = mu[site * 3 + 1];
    const float mu2 = mu[site * 3 + 2];
    const ull mu0p = pk2(mu0, mu0), mu1p = pk2(mu1, mu1), mu2p = pk2(mu2, mu2);

    ull Z2 = 0ull, sw0p = 0ull, sw1p = 0ull, sw2p = 0ull;
    ull s00p = 0ull, s01p = 0ull, s02p = 0ull, s11p = 0ull, s12p = 0ull, s22p = 0ull;

    for (int ch = 0; ch < 4; ch++) {
        __syncthreads();
        for (int vv = threadIdx.x; vv < 2048; vv += 256) {
            const float* wp = W + (size_t)(ch * 2048 + vv) * 3;
            sW0[vv] = wp[0];
            sW1[vv] = wp[1];
            sW2[vv] = wp[2];
        }
        __syncthreads();
#pragma unroll 2
        for (int it = 0; it < 16; it++) {
            int v = it * 128 + lane * 4;
            float4 w0 = *(const float4*)&sW0[v];
            float4 w1 = *(const float4*)&sW1[v];
            float4 w2 = *(const float4*)&sW2[v];
#pragma unroll
            for (int h = 0; h < 2; h++) {
                ull w0p = h ? pk2(w0.z, w0.w) : pk2(w0.x, w0.y);
                ull w1p = h ? pk2(w1.z, w1.w) : pk2(w1.x, w1.y);
                ull w2p = h ? pk2(w2.z, w2.w) : pk2(w2.x, w2.y);
                ull l = fma2(mu0p, w0p, fma2(mu1p, w1p, mul2(mu2p, w2p)));
                float l0, l1;
                upk2(l, l0, l1);
                ull ep = pk2(__expf(l0), __expf(l1));
                Z2 = add2(Z2, ep);
                ull t0 = mul2(ep, w0p);
                ull t1 = mul2(ep, w1p);
                ull t2 = mul2(ep, w2p);
                sw0p = add2(sw0p, t0);
                sw1p = add2(sw1p, t1);
                sw2p = add2(sw2p, t2);
                s00p = fma2(t0, w0p, s00p);
                s01p = fma2(t0, w1p, s01p);
                s02p = fma2(t0, w2p, s02p);
                s11p = fma2(t1, w1p, s11p);
                s12p = fma2(t1, w2p, s12p);
                s22p = fma2(t2, w2p, s22p);
            }
        }
    }
    float x, y;
    float Z, sw0, sw1, sw2, s00, s01, s02, s11, s12, s22;
    upk2(Z2, x, y);  Z   = x + y;
    upk2(sw0p, x, y); sw0 = x + y;
    upk2(sw1p, x, y); sw1 = x + y;
    upk2(sw2p, x, y); sw2 = x + y;
    upk2(s00p, x, y); s00 = x + y;
    upk2(s01p, x, y); s01 = x + y;
    upk2(s02p, x, y); s02 = x + y;
    upk2(s11p, x, y); s11 = x + y;
    upk2(s12p, x, y); s12 = x + y;
    upk2(s22p, x, y); s22 = x + y;

#pragma unroll
    for (int off = 16; off; off >>= 1) {
        Z += __shfl_xor_sync(~0u, Z, off);
        sw0 += __shfl_xor_sync(~0u, sw0, off);
        sw1 += __shfl_xor_sync(~0u, sw1, off);
        sw2 += __shfl_xor_sync(~0u, sw2, off);
        s00 += __shfl_xor_sync(~0u, s00, off);
        s01 += __shfl_xor_sync(~0u, s01, off);
        s02 += __shfl_xor_sync(~0u, s02, off);
        s11 += __shfl_xor_sync(~0u, s11, off);
        s12 += __shfl_xor_sync(~0u, s12, off);
        s22 += __shfl_xor_sync(~0u, s22, off);
    }

    if (lane == 0) {
        float Zi = 1.0f / Z;
        float m0 = sw0 * Zi, m1 = sw1 * Zi, m2 = sw2 * Zi;
        float Lo[9];
        Lo[0] = s00 * Zi - m0 * m0 + 1e-6f;
        Lo[1] = s01 * Zi - m0 * m1;
        Lo[2] = s02 * Zi - m0 * m2;
        Lo[3] = Lo[1];
        Lo[4] = s11 * Zi - m1 * m1 + 1e-6f;
        Lo[5] = s12 * Zi - m1 * m2;
        Lo[6] = Lo[2];
        Lo[7] = Lo[5];
        Lo[8] = s22 * Zi - m2 * m2 + 1e-6f;

        float a[9], Lp[9];
#pragma unroll
        for (int k = 0; k < 9; k++) a[k] = Sp[site * 9 + k];
        a[0] += 1e-6f; a[4] += 1e-6f; a[8] += 1e-6f;
        inv3(a, Lp);

        float Lq[9];
#pragma unroll
        for (int k = 0; k < 9; k++) a[k] = Sq[site * 9 + k];
        a[0] += 1e-6f; a[4] += 1e-6f; a[8] += 1e-6f;
        inv3(a, Lq);

        float R[9];
        rodrigues(phi[site * 3 + 0], phi[site * 3 + 1], phi[site * 3 + 2], R);

        float T[9], Smat[9];
        mm3(Lq, R, T);
        mTm3(R, T, Smat);

#pragma unroll
        for (int k = 0; k < 9; k++) {
            g_Abase[site * 9 + k] = Lp[k] + Lo[k];
            g_Lq[site * 9 + k] = Lq[k];
            g_R[site * 9 + k] = R[k];
            g_S[site * 9 + k] = Smat[k];
        }
    }
}

// ==== K2: fused beta@S GEMM + final assembly/inverse ====
// 128 blocks x 256 threads; warp handles 2 rows; S chunked as 9 transposed smem planes.
__global__ void __launch_bounds__(256) k2_kernel(const float* __restrict__ beta,
                                                 float* __restrict__ out) {
    __shared__ float sS[9][1024];
    const int warp = threadIdx.x >> 5;
    const int lane = threadIdx.x & 31;
    const int row0 = blockIdx.x * 16 + warp * 2;

    ull acc[2][9];
#pragma unroll
    for (int r = 0; r < 2; r++)
#pragma unroll
        for (int k = 0; k < 9; k++) acc[r][k] = 0ull;

    for (int ch = 0; ch < 2; ch++) {
        __syncthreads();
        for (int idx = threadIdx.x; idx < 9216; idx += 256) {
            int j = idx / 9;
            int k = idx - 9 * j;
            sS[k][j] = g_S[(size_t)(ch * 1024 + j) * 9 + k];
        }
        __syncthreads();
        const float* b0p = beta + (size_t)row0 * NS + ch * 1024;
        const float* b1p = b0p + NS;
#pragma unroll 2
        for (int jj = lane * 4; jj < 1024; jj += 128) {
            float4 b0 = *(const float4*)(b0p + jj);
            float4 b1 = *(const float4*)(b1p + jj);
            ull b0a = pk2(b0.x, b0.y), b0b = pk2(b0.z, b0.w);
            ull b1a = pk2(b1.x, b1.y), b1b = pk2(b1.z, b1.w);
#pragma unroll
            for (int k = 0; k < 9; k++) {
                float4 s = *(const float4*)&sS[k][jj];
                ull sa = pk2(s.x, s.y), sb = pk2(s.z, s.w);
                acc[0][k] = fma2(b0a, sa, acc[0][k]);
                acc[0][k] = fma2(b0b, sb, acc[0][k]);
                acc[1][k] = fma2(b1a, sa, acc[1][k]);
                acc[1][k] = fma2(b1b, sb, acc[1][k]);
            }
        }
    }

    float c[2][9];
#pragma unroll
    for (int r = 0; r < 2; r++)
#pragma unroll
        for (int k = 0; k < 9; k++) {
            float lo, hi;
            upk2(acc[r][k], lo, hi);
            c[r][k] = lo + hi;
        }
#pragma unroll
    for (int r = 0; r < 2; r++)
#pragma unroll
        for (int k = 0; k < 9; k++)
#pragma unroll
            for (int off = 16; off; off >>= 1)
                c[r][k] += __shfl_xor_sync(~0u, c[r][k], off);

    if (lane < 2) {
        const int i = row0 + lane;
        float cs = 0.f;
#pragma unroll
        for (int p = 0; p < 32; p++) cs += g_colpart[p * NS + i];

        float R[9], Lq[9], Ab[9], C[9];
#pragma unroll
        for (int k = 0; k < 9; k++) {
            R[k] = g_R[i * 9 + k];
            Lq[k] = g_Lq[i * 9 + k];
            Ab[k] = g_Abase[i * 9 + k];
            C[k] = c[lane][k];
        }

        float T[9], Min[9];
        mm3(R, C, T);
        mmT3(T, R, Min);

        float M[9];
#pragma unroll
        for (int k = 0; k < 9; k++) M[k] = Ab[k] + Min[k] + cs * Lq[k];

        float Ms[9];
#pragma unroll
        for (int r = 0; r < 3; r++)
#pragma unroll
            for (int cc = 0; cc < 3; cc++)
                Ms[r * 3 + cc] = 0.5f * (M[r * 3 + cc] + M[cc * 3 + r]);

#pragma unroll
        for (int k = 0; k < 9; k++)
            if (!isfinite(Ms[k])) Ms[k] = (k == 0 || k == 4 || k == 8) ? 1.0f : 0.0f;
        Ms[0] += 1e-4f; Ms[4] += 1e-4f; Ms[8] += 1e-4f;

        float Mi[9];
        inv3(Ms, Mi);

#pragma unroll
        for (int k = 0; k < 9; k++) {
            out[i * 9 + k] = Ms[k];
            out[NS * 9 + i * 9 + k] = Mi[k];
        }
    }
}

extern "C" void kernel_launch(void* const* d_in, const int* in_sizes, int n_in,
                              void* d_out, int out_size) {
    const float* Sp = (const float*)d_in[0];
    const float* Sq = (const float*)d_in[1];
    const float* phi = (const float*)d_in[2];
    const float* beta = (const float*)d_in[3];
    const float* mu = (const float*)d_in[4];
    const float* W = (const float*)d_in[5];
    float* out = (float*)d_out;

    k1_kernel<<<288, 256>>>(Sp, Sq, phi, mu, W, beta);
    k2_kernel<<<128, 256>>>(beta, out);
}